// round 2
// baseline (speedup 1.0000x reference)
#include <cuda_runtime.h>

#define BIGV 1e10f
#define TT 1024
#define BB 32
#define DD 64
#define NDIAG 2047   // row+col in [0, 2046]

// Diagonal-major cost scratch: g_cost[b][d][row], d = row+col.
// 32 * 2047 * 1024 floats = 268 MB (static __device__ scratch, sanctioned).
static __device__ float g_cost[(size_t)BB * NDIAG * TT];

// ---------------------------------------------------------------------------
// Kernel A: cost matrix, 64x64 tiles, 4x4 register tiling, K=64 fully in smem.
// Writes results in anti-diagonal-major layout so the DP kernel reads coalesced.
// ---------------------------------------------------------------------------
__global__ __launch_bounds__(256) void cost_kernel(const float* __restrict__ x,
                                                   const float* __restrict__ y) {
    const int bz = blockIdx.z;   // batch
    const int br = blockIdx.y;   // row tile (16)
    const int bc = blockIdx.x;   // col tile (16)
    const int tid = threadIdx.x; // 256 threads

    __shared__ float arena[2 * 64 * 65];          // 33.3 KB
    __shared__ float x2s[64], y2s[64];
    float* xsT = arena;                           // xsT[k*65 + r]
    float* ysT = arena + 64 * 65;                 // ysT[k*65 + c]
    float (*res)[72] = (float (*)[72])arena;      // res[64][72] aliases arena

    const float* xb = x + ((size_t)bz * TT + br * 64) * DD;
    const float* yb = y + ((size_t)bz * TT + bc * 64) * DD;

    #pragma unroll
    for (int i = 0; i < 16; i++) {
        int idx = tid + i * 256;   // 0..4095
        int r = idx >> 6;
        int d = idx & 63;
        xsT[d * 65 + r] = xb[r * DD + d];
        ysT[d * 65 + r] = yb[r * DD + d];
    }
    __syncthreads();

    if (tid < 64) {
        float s = 0.f;
        #pragma unroll
        for (int k = 0; k < 64; k++) { float v = xsT[k * 65 + tid]; s = fmaf(v, v, s); }
        x2s[tid] = s;
    } else if (tid < 128) {
        int c = tid - 64;
        float s = 0.f;
        #pragma unroll
        for (int k = 0; k < 64; k++) { float v = ysT[k * 65 + c]; s = fmaf(v, v, s); }
        y2s[c] = s;
    }

    const int tx = tid & 15;   // col group
    const int ty = tid >> 4;   // row group
    float acc[4][4] = {};
    #pragma unroll
    for (int k = 0; k < 64; k++) {
        float xr[4], yc[4];
        #pragma unroll
        for (int r = 0; r < 4; r++) xr[r] = xsT[k * 65 + ty * 4 + r];
        #pragma unroll
        for (int c = 0; c < 4; c++) yc[c] = ysT[k * 65 + tx * 4 + c];
        #pragma unroll
        for (int r = 0; r < 4; r++)
            #pragma unroll
            for (int c = 0; c < 4; c++)
                acc[r][c] = fmaf(xr[r], yc[c], acc[r][c]);
    }
    __syncthreads();

    float xr2[4], yc2[4];
    #pragma unroll
    for (int r = 0; r < 4; r++) xr2[r] = x2s[ty * 4 + r];
    #pragma unroll
    for (int c = 0; c < 4; c++) yc2[c] = y2s[tx * 4 + c];
    #pragma unroll
    for (int r = 0; r < 4; r++)
        #pragma unroll
        for (int c = 0; c < 4; c++)
            res[ty * 4 + r][tx * 4 + c] =
                fmaxf(xr2[r] + yc2[c] - 2.0f * acc[r][c], 0.0f);
    __syncthreads();

    const int wid = tid >> 5, lane = tid & 31;
    const int dbase = br * 64 + bc * 64;
    for (int dl = wid; dl < 127; dl += 8) {
        int rlo = dl > 63 ? dl - 63 : 0;
        int rhi = dl < 63 ? dl : 63;
        size_t gbase = ((size_t)bz * NDIAG + (dbase + dl)) * TT + (size_t)br * 64;
        for (int r0 = rlo; r0 <= rhi; r0 += 32) {
            int r = r0 + lane;
            if (r <= rhi) g_cost[gbase + r] = res[r][dl - r];
        }
    }
}

// ---------------------------------------------------------------------------
// Kernel B: anti-diagonal DP, register-resident. One CTA (256 threads) per
// batch; thread t owns rows 4t..4t+3 (DP indices 4t+1..4t+4). DP state in
// registers; left halo via shfl within warp, double-buffered smem across
// warps; one __syncthreads per diagonal.
// softmin uses the exp(0)=1 identity: s = 1 + e^(mn-mid) + e^(mn-hi).
// ---------------------------------------------------------------------------
__global__ __launch_bounds__(256) void dp_kernel(float* __restrict__ out) {
    const int b = blockIdx.x;
    const int t = threadIdx.x;        // 0..255
    const int lane = t & 31;
    const int w = t >> 5;             // warp 0..7
    const int r0 = t << 2;            // first owned row

    __shared__ float halo[2][8];

    // v1[j] = d_{k-1}[r0+j+1], v2[j] = d_{k-2}[r0+j+1]
    float v1[4], v2[4];
    #pragma unroll
    for (int j = 0; j < 4; j++) { v1[j] = BIGV; v2[j] = BIGV; }
    float L1 = BIGV;                     // d_{k-1}[r0]
    float L2 = (t == 0) ? 0.0f : BIGV;   // d_{k-2}[r0]   (d0[0] = 0)

    const float* costbase = g_cost + (size_t)b * NDIAG * TT + r0;

    // prefetch cost for k = 2 (diag plane 0); loads always in-bounds,
    // invalid lanes are masked at use.
    float4 pref = *(const float4*)(costbase);
    float res = BIGV;

    for (int k = 2; k <= 2 * TT; k++) {
        float4 cost = pref;
        if (k < 2 * TT)
            pref = *(const float4*)(costbase + (size_t)(k - 1) * TT);

        // valid rows on diagonal k: r in [k-1-T, k-2]
        const int rlo = k - 1 - TT;
        const int rhi = k - 2;

        float cur[4];
        if ((r0 <= rhi) & (r0 + 3 >= rlo)) {
            const float* cp = (const float*)&cost;
            #pragma unroll
            for (int j = 0; j < 4; j++) {
                float a  = (j == 0) ? L2 : v2[j - 1];  // d_{k-2}[idx-1]
                float bb = (j == 0) ? L1 : v1[j - 1];  // d_{k-1}[idx-1]
                float c  = v1[j];                      // d_{k-1}[idx]
                float mnab = fminf(a, bb);
                float mxab = fmaxf(a, bb);
                float mn   = fminf(mnab, c);
                float hi   = fmaxf(mxab, c);
                float mid  = fmaxf(mnab, fminf(mxab, c));
                float s  = 1.0f + __expf(mn - mid) + __expf(mn - hi);
                float sm = mn - __logf(s);
                int r = r0 + j;
                cur[j] = ((r >= rlo) & (r <= rhi)) ? cp[j] + sm : BIGV;
            }
        } else {
            cur[0] = cur[1] = cur[2] = cur[3] = BIGV;
        }

        // halo exchange: new d_k[r0] is neighbor thread's cur[3]
        float nb = __shfl_up_sync(0xffffffffu, cur[3], 1);
        if (lane == 31) halo[k & 1][w] = cur[3];
        __syncthreads();
        if (lane == 0) nb = (w == 0) ? BIGV : halo[k & 1][w - 1];

        L2 = L1;
        L1 = nb;
        #pragma unroll
        for (int j = 0; j < 4; j++) { v2[j] = v1[j]; v1[j] = cur[j]; }
        res = cur[3];
    }

    // answer = d_{2T}[T] : idx 1024 -> r = 1023 -> thread 255, j = 3
    if (t == 255) out[b] = res;
}

extern "C" void kernel_launch(void* const* d_in, const int* in_sizes, int n_in,
                              void* d_out, int out_size) {
    const float* x = (const float*)d_in[0];
    const float* y = (const float*)d_in[1];
    float* out = (float*)d_out;

    dim3 gridA(TT / 64, TT / 64, BB);   // (16, 16, 32)
    cost_kernel<<<gridA, 256>>>(x, y);
    dp_kernel<<<BB, 256>>>(out);
}

// round 3
// speedup vs baseline: 1.0499x; 1.0499x over previous
#include <cuda_runtime.h>

#define BIGV 1e10f
#define TT 1024
#define BB 32
#define DD 64
#define NDIAG 2047   // row+col in [0, 2046]

// Diagonal-major cost scratch: g_cost[b][d][row], d = row+col.
// 32 * 2047 * 1024 floats = 268 MB (static __device__ scratch, sanctioned).
static __device__ float g_cost[(size_t)BB * NDIAG * TT];

// ---------------------------------------------------------------------------
// Kernel A: cost matrix, 64x64 tiles, 4x4 register tiling, K=64 fully in smem.
// Writes results in anti-diagonal-major layout so the DP kernel reads coalesced.
// ---------------------------------------------------------------------------
__global__ __launch_bounds__(256) void cost_kernel(const float* __restrict__ x,
                                                   const float* __restrict__ y) {
    const int bz = blockIdx.z;   // batch
    const int br = blockIdx.y;   // row tile (16)
    const int bc = blockIdx.x;   // col tile (16)
    const int tid = threadIdx.x; // 256 threads

    __shared__ float arena[2 * 64 * 65];          // 33.3 KB
    __shared__ float x2s[64], y2s[64];
    float* xsT = arena;                           // xsT[k*65 + r]
    float* ysT = arena + 64 * 65;                 // ysT[k*65 + c]
    float (*res)[72] = (float (*)[72])arena;      // res[64][72] aliases arena

    const float* xb = x + ((size_t)bz * TT + br * 64) * DD;
    const float* yb = y + ((size_t)bz * TT + bc * 64) * DD;

    #pragma unroll
    for (int i = 0; i < 16; i++) {
        int idx = tid + i * 256;   // 0..4095
        int r = idx >> 6;
        int d = idx & 63;
        xsT[d * 65 + r] = xb[r * DD + d];
        ysT[d * 65 + r] = yb[r * DD + d];
    }
    __syncthreads();

    if (tid < 64) {
        float s = 0.f;
        #pragma unroll
        for (int k = 0; k < 64; k++) { float v = xsT[k * 65 + tid]; s = fmaf(v, v, s); }
        x2s[tid] = s;
    } else if (tid < 128) {
        int c = tid - 64;
        float s = 0.f;
        #pragma unroll
        for (int k = 0; k < 64; k++) { float v = ysT[k * 65 + c]; s = fmaf(v, v, s); }
        y2s[c] = s;
    }

    const int tx = tid & 15;   // col group
    const int ty = tid >> 4;   // row group
    float acc[4][4] = {};
    #pragma unroll
    for (int k = 0; k < 64; k++) {
        float xr[4], yc[4];
        #pragma unroll
        for (int r = 0; r < 4; r++) xr[r] = xsT[k * 65 + ty * 4 + r];
        #pragma unroll
        for (int c = 0; c < 4; c++) yc[c] = ysT[k * 65 + tx * 4 + c];
        #pragma unroll
        for (int r = 0; r < 4; r++)
            #pragma unroll
            for (int c = 0; c < 4; c++)
                acc[r][c] = fmaf(xr[r], yc[c], acc[r][c]);
    }
    __syncthreads();

    float xr2[4], yc2[4];
    #pragma unroll
    for (int r = 0; r < 4; r++) xr2[r] = x2s[ty * 4 + r];
    #pragma unroll
    for (int c = 0; c < 4; c++) yc2[c] = y2s[tx * 4 + c];
    #pragma unroll
    for (int r = 0; r < 4; r++)
        #pragma unroll
        for (int c = 0; c < 4; c++)
            res[ty * 4 + r][tx * 4 + c] =
                fmaxf(xr2[r] + yc2[c] - 2.0f * acc[r][c], 0.0f);
    __syncthreads();

    const int wid = tid >> 5, lane = tid & 31;
    const int dbase = br * 64 + bc * 64;
    for (int dl = wid; dl < 127; dl += 8) {
        int rlo = dl > 63 ? dl - 63 : 0;
        int rhi = dl < 63 ? dl : 63;
        size_t gbase = ((size_t)bz * NDIAG + (dbase + dl)) * TT + (size_t)br * 64;
        for (int r0 = rlo; r0 <= rhi; r0 += 32) {
            int r = r0 + lane;
            if (r <= rhi) g_cost[gbase + r] = res[r][dl - r];
        }
    }
}

// ---------------------------------------------------------------------------
// Kernel B: anti-diagonal DP, register-resident, 4 rows/thread, 256 thr/CTA.
// Depth-3 prefetch ring on the cost loads (DRAM latency ~380-580 cyc must be
// covered by ~3 diagonals of compute). Loads issued only for diagonals where
// the thread has valid cells. softmin via exp(0)=1 identity (3 MUFU/cell).
// ---------------------------------------------------------------------------
__global__ __launch_bounds__(256) void dp_kernel(float* __restrict__ out) {
    const int b = blockIdx.x;
    const int t = threadIdx.x;        // 0..255
    const int lane = t & 31;
    const int w = t >> 5;             // warp 0..7
    const int r0 = t << 2;            // first owned row

    __shared__ float halo[2][8];

    // v1[j] = d_{k-1}[r0+j+1], v2[j] = d_{k-2}[r0+j+1]
    float v1[4], v2[4];
    #pragma unroll
    for (int j = 0; j < 4; j++) { v1[j] = BIGV; v2[j] = BIGV; }
    float L1 = BIGV;                     // d_{k-1}[r0]
    float L2 = (t == 0) ? 0.0f : BIGV;   // d_{k-2}[r0]   (d0[0] = 0)

    const float* costbase = g_cost + (size_t)b * NDIAG * TT + r0;

    // Thread has valid cells on diag k iff k in [kminA, kmaxA].
    const int kminA = r0 + 2;
    const int kmaxA = r0 + 4 + TT;

    // Prefetch ring: pf0 -> diag k, pf1 -> k+1, pf2 -> k+2. Plane of diag k is k-2.
    float4 pf0 = make_float4(0, 0, 0, 0), pf1 = pf0, pf2 = pf0;
    if (2 >= kminA) pf0 = *(const float4*)(costbase);
    if (3 >= kminA) pf1 = *(const float4*)(costbase + (size_t)1 * TT);
    if (4 >= kminA) pf2 = *(const float4*)(costbase + (size_t)2 * TT);

    float res = BIGV;

    #pragma unroll 3
    for (int k = 2; k <= 2 * TT; k++) {
        float4 cost = pf0;
        pf0 = pf1; pf1 = pf2;
        // issue load for diag k+3 (consumed 3 iterations from now)
        const int kd = k + 3;
        if ((kd <= 2 * TT) & (kd >= kminA) & (kd <= kmaxA))
            pf2 = *(const float4*)(costbase + (size_t)(kd - 2) * TT);

        // valid rows on diagonal k: r in [k-1-T, k-2]
        const int rlo = k - 1 - TT;
        const int rhi = k - 2;

        float cur[4];
        if ((k >= kminA) & (k <= kmaxA)) {
            const float* cp = (const float*)&cost;
            #pragma unroll
            for (int j = 0; j < 4; j++) {
                float a  = (j == 0) ? L2 : v2[j - 1];  // d_{k-2}[idx-1]
                float bb = (j == 0) ? L1 : v1[j - 1];  // d_{k-1}[idx-1]
                float c  = v1[j];                      // d_{k-1}[idx]
                float mnab = fminf(a, bb);
                float mxab = fmaxf(a, bb);
                float mn   = fminf(mnab, c);
                float hi   = fmaxf(mxab, c);
                float mid  = fmaxf(mnab, fminf(mxab, c));
                float s  = 1.0f + __expf(mn - mid) + __expf(mn - hi);
                float sm = mn - __logf(s);
                int r = r0 + j;
                cur[j] = ((r >= rlo) & (r <= rhi)) ? cp[j] + sm : BIGV;
            }
            res = cur[3];
        } else {
            cur[0] = cur[1] = cur[2] = cur[3] = BIGV;
        }

        // halo exchange: new d_k[r0] is neighbor thread's cur[3]
        float nb = __shfl_up_sync(0xffffffffu, cur[3], 1);
        if (lane == 31) halo[k & 1][w] = cur[3];
        __syncthreads();
        if (lane == 0) nb = (w == 0) ? BIGV : halo[k & 1][w - 1];

        L2 = L1;
        L1 = nb;
        #pragma unroll
        for (int j = 0; j < 4; j++) { v2[j] = v1[j]; v1[j] = cur[j]; }
    }

    // answer = d_{2T}[T] : idx 1024 -> r = 1023 -> thread 255, j = 3 (k = 2048)
    if (t == 255) out[b] = res;
}

extern "C" void kernel_launch(void* const* d_in, const int* in_sizes, int n_in,
                              void* d_out, int out_size) {
    const float* x = (const float*)d_in[0];
    const float* y = (const float*)d_in[1];
    float* out = (float*)d_out;

    dim3 gridA(TT / 64, TT / 64, BB);   // (16, 16, 32)
    cost_kernel<<<gridA, 256>>>(x, y);
    dp_kernel<<<BB, 256>>>(out);
}